// round 9
// baseline (speedup 1.0000x reference)
#include <cuda_runtime.h>
#include <stdint.h>

// FieldAwareFM: B=16384, F=10, D=8.
// out[b] = b_lin + sum_f w[idx_f] + sum_{f<g} <emb[f][idx_g], emb[g][idx_f]>
//
// R1-R7: runtime (~19us) invariant to gather mechanism / cache state ->
// bound by scattered-sector miss processing. This round: loads whose COLUMN
// field is 5..9 (45 of 90 per sample) are redirected to a per-launch
// transposed block g_concat[j][f][8] = emb[f][185000+j] (fields 5-9 span
// global rows [185000,188610), 3610 rows x 10 tables x 32B = 1.16MB).
// For one sample+column, the 9 needed rows become 288B contiguous (3 cache
// lines) instead of 9 lines 6MB apart -> same-line sector merging cuts
// primary miss work ~3x for those columns; region is L2/L1-hot.
//
// Main kernel keeps the R7 half-split layout: slot = 32t+lane, pair p=slot>>1,
// h=slot&1. Lane loads 16B half h of both rows of its pair and accumulates the
// partial dot locally; halves combine in the final warp reduction.

#define BATCH       16384
#define NUM_FIELDS  10
#define INPUT_DIM   188610
#define NUM_PAIRS   45
#define NUM_ROUNDS  3
#define CONCAT_ROWS 3610
#define CONCAT_G0   185000   // global index of first concat row (field 5 base)

__device__ __align__(16) float g_concat[CONCAT_ROWS * 80];   // [j][f][8], 1.16MB

__constant__ int c_offsets[NUM_FIELDS] = {
    0, 100000, 150000, 170000, 180000, 185000, 187000, 188000, 188500, 188600
};

// pair p -> (f, g), f < g   (pad p=45..47 -> (0,1), masked in accumulate)
__constant__ signed char c_pf[48] = {
    0,0,0,0,0,0,0,0,0, 1,1,1,1,1,1,1,1, 2,2,2,2,2,2,2, 3,3,3,3,3,3,
    4,4,4,4,4, 5,5,5,5, 6,6,6, 7,7, 8, 0,0,0
};
__constant__ signed char c_pg[48] = {
    1,2,3,4,5,6,7,8,9, 2,3,4,5,6,7,8,9, 3,4,5,6,7,8,9, 4,5,6,7,8,9,
    5,6,7,8,9, 6,7,8,9, 7,8,9, 8,9, 9, 1,1,1
};

// ---- pre-kernel: build transposed hot block (streaming copy, ~2.3MB) ----
__global__ __launch_bounds__(256)
void build_concat(const float* __restrict__ emb)
{
    const int u = blockIdx.x * 256 + threadIdx.x;     // (f, j, h)
    if (u >= NUM_FIELDS * CONCAT_ROWS * 2) return;
    const int f   = u / (CONCAT_ROWS * 2);
    const int rem = u - f * (CONCAT_ROWS * 2);
    const int j   = rem >> 1;
    const int h   = rem & 1;
    const float4 v = *(const float4*)
        (emb + ((size_t)f * INPUT_DIM + CONCAT_G0 + (size_t)j) * 8 + h * 4);
    *(float4*)(g_concat + (size_t)j * 80 + f * 8 + h * 4) = v;
}

__global__ __launch_bounds__(256)
void ffm_kernel(const int* __restrict__ x,
                const float* __restrict__ w,
                const float* __restrict__ b_lin,
                const float* __restrict__ emb,
                float* __restrict__ out)
{
    const int warp_in_block = threadIdx.x >> 5;
    const int lane          = threadIdx.x & 31;
    const int b             = blockIdx.x * (blockDim.x >> 5) + warp_in_block;
    const unsigned full     = 0xffffffffu;

    const float bias = __ldg(&b_lin[0]);

    // lanes 0..9: this sample's global indices (coalesced 40B)
    int my_gid = 0;
    if (lane < NUM_FIELDS) {
        my_gid = x[b * NUM_FIELDS + lane] + c_offsets[lane];
    }
    // linear gather (independent, issues early)
    float lin = 0.0f;
    if (lane < NUM_FIELDS) {
        lin = __ldg(&w[my_gid]);
    }

    const int h = lane & 1;   // 16B half of the 32B row

    // ---- Phase A: decode pairs, compute addresses, issue all 6 loads ----
    const float4* pa[NUM_ROUNDS];
    const float4* pb[NUM_ROUNDS];
    bool valid[NUM_ROUNDS];
#pragma unroll
    for (int t = 0; t < NUM_ROUNDS; t++) {
        const int p = ((t << 5) + lane) >> 1;       // pair index
        const int f = (int)c_pf[p];
        const int g = (int)c_pg[p];
        const int gid_g = __shfl_sync(full, my_gid, g);
        const int gid_f = __shfl_sync(full, my_gid, f);
        valid[t] = (p < NUM_PAIRS);
        // side A: emb[f][idx_g]  (column field g)
        pa[t] = (g >= 5)
            ? (const float4*)(g_concat + (size_t)(gid_g - CONCAT_G0) * 80 + f * 8 + h * 4)
            : (const float4*)(emb + ((size_t)f * INPUT_DIM + (size_t)gid_g) * 8 + h * 4);
        // side B: emb[g][idx_f]  (column field f)
        pb[t] = (f >= 5)
            ? (const float4*)(g_concat + (size_t)(gid_f - CONCAT_G0) * 80 + g * 8 + h * 4)
            : (const float4*)(emb + ((size_t)g * INPUT_DIM + (size_t)gid_f) * 8 + h * 4);
    }

    float4 va[NUM_ROUNDS], vb[NUM_ROUNDS];
#pragma unroll
    for (int t = 0; t < NUM_ROUNDS; t++) {
        va[t] = __ldg(pa[t]);
        vb[t] = __ldg(pb[t]);
    }

    // ---- Phase B: local partial dots (no exchange) ----
    float ffm = 0.0f;
#pragma unroll
    for (int t = 0; t < NUM_ROUNDS; t++) {
        float d = va[t].x * vb[t].x + va[t].y * vb[t].y
                + va[t].z * vb[t].z + va[t].w * vb[t].w;
        if (valid[t]) ffm += d;
    }

    float acc = ffm + lin;

    // warp reduction (combines pair halves + linear lanes)
#pragma unroll
    for (int off = 16; off > 0; off >>= 1) {
        acc += __shfl_xor_sync(full, acc, off);
    }

    if (lane == 0) {
        out[b] = acc + bias;
    }
}

extern "C" void kernel_launch(void* const* d_in, const int* in_sizes, int n_in,
                              void* d_out, int out_size)
{
    (void)in_sizes; (void)n_in; (void)out_size;
    const int*   x     = (const int*)d_in[0];
    const float* w     = (const float*)d_in[1];
    const float* b_lin = (const float*)d_in[2];
    const float* emb   = (const float*)d_in[3];
    float*       out   = (float*)d_out;

    // 1) build the transposed hot block for fields 5..9 (deterministic, per launch)
    const int units = NUM_FIELDS * CONCAT_ROWS * 2;          // 72200
    build_concat<<<(units + 255) / 256, 256>>>(emb);

    // 2) main kernel
    const int warps_per_block = 8;                // 256 threads
    const int blocks = BATCH / warps_per_block;   // 2048
    ffm_kernel<<<blocks, warps_per_block * 32>>>(x, w, b_lin, emb, out);
}